// round 13
// baseline (speedup 1.0000x reference)
#include <cuda_runtime.h>
#include <cuda_fp16.h>
#include <math.h>
#include <stdint.h>

// ---------------------------------------------------------------------------
// ReDrafterHead: 2-layer GRU draft head + big vocab projection.
// B=64, HIDDEN=4096, DH=512, VOCAB=50257, NUM_DRAFT=4.
//
// Round 13:
//  - Gates HMMA fused with combine: one CTA owns j-range 4, computes BOTH
//    gi (via A1) and gh (via A2) as N=16+16 padded tiles; gates stay in
//    SMEM epi; combine in-CTA. 10 grid barriers (was 18), no g_gates.
//  - 3-stage cp.async pipeline (dynamic smem 67.5KB) hides L2 latency.
//  - h states double-buffered (fp32 + fp16 hi/lo). x as fp16 hi/lo global.
//  - logits: unchanged single-fp16 HMMA (CTA 128x128, 2 CTAs/SM).
// ---------------------------------------------------------------------------

#define B_      64
#define HID     4096
#define DH      512
#define VOCAB   50257
#define NDRAFT  4
#define GRIDN   128
#define G3      1536

__device__ float  g_h0f[2][B_ * DH], g_h1f[2][B_ * DH];
__device__ __half g_h0h[2][B_ * DH], g_h0l[2][B_ * DH];
__device__ __half g_h1h[2][B_ * DH], g_h1l[2][B_ * DH];
__device__ __half g_xh[B_ * DH],  g_xl[B_ * DH];
__device__ float  g_part[16 * B_ * DH];     // ip split-K partials
__device__ __half g_Ah[B_ * NDRAFT * DH];   // logits A fp16, m = b*4+step
__device__ __half g_wih0h[G3 * DH], g_whh0h[G3 * DH];
__device__ __half g_wih1h[G3 * DH], g_whh1h[G3 * DH];
__device__ unsigned int g_bcount;           // monotonic barrier counter

__device__ __forceinline__ float sigmoidf_(float v) { return 1.0f / (1.0f + __expf(-v)); }

__device__ __forceinline__ uint32_t pack_f16x2(__half lo, __half hi) {
    return ((uint32_t)__half_as_ushort(hi) << 16) | (uint32_t)__half_as_ushort(lo);
}
__device__ __forceinline__ uint32_t smem_to_u32(const void* p) {
    uint32_t a;
    asm("{ .reg .u64 t; cvta.to.shared.u64 t, %1; cvt.u32.u64 %0, t; }" : "=r"(a) : "l"(p));
    return a;
}
__device__ __forceinline__ void ldsm4(uint32_t* r, uint32_t addr) {
    asm volatile("ldmatrix.sync.aligned.m8n8.x4.shared.b16 {%0,%1,%2,%3}, [%4];"
        : "=r"(r[0]), "=r"(r[1]), "=r"(r[2]), "=r"(r[3]) : "r"(addr));
}
__device__ __forceinline__ void mma16816h(float* d, const uint32_t* a, const uint32_t* b) {
    asm volatile("mma.sync.aligned.m16n8k16.row.col.f32.f16.f16.f32 "
        "{%0,%1,%2,%3}, {%4,%5,%6,%7}, {%8,%9}, {%0,%1,%2,%3};"
        : "+f"(d[0]), "+f"(d[1]), "+f"(d[2]), "+f"(d[3])
        : "r"(a[0]), "r"(a[1]), "r"(a[2]), "r"(a[3]), "r"(b[0]), "r"(b[1]));
}

// Grid-wide barrier: monotonic counter (graph-replay safe; GRIDN co-resident).
__device__ __forceinline__ void grid_barrier(int tid) {
    __syncthreads();
    if (tid == 0) {
        __threadfence();
        unsigned int old = atomicAdd(&g_bcount, 1u);
        unsigned int target = (old / GRIDN + 1u) * GRIDN;
        unsigned int v;
        do {
            asm volatile("ld.acquire.gpu.global.u32 %0, [%1];" : "=r"(v) : "l"(&g_bcount));
        } while (v < target);
    }
    __syncthreads();
}

// ---------------------------------------------------------------------------
// Dynamic smem layout for gru_fused (3-stage, 80B rows):
//   A1H: st*5120        A1L: 15360+st*5120   A2H: 30720+st*5120
//   A2L: 46080+st*5120  WI: 61440+st*1280    WH: 65280+st*1280
// total 69120. epi (float[64][25] = 6400B) aliases offset 0 post-compute.
// ip phase uses [0, 16384).
#define GA_A1H(st) ((st) * 5120)
#define GA_A1L(st) (15360 + (st) * 5120)
#define GA_A2H(st) (30720 + (st) * 5120)
#define GA_A2L(st) (46080 + (st) * 5120)
#define GA_WI(st)  (61440 + (st) * 1280)
#define GA_WH(st)  (65280 + (st) * 1280)
#define GRU_SMEM   69120

// ---------------------------------------------------------------------------
// Fused gates+combine. CTA owns j-range [jb, jb+4).
// GEMM: C[64 x (16+16 pad)] ; gi cols via A1 (hi+lo), gh cols via A2 (hi+lo),
// W rows rr = gate*4 + j (rows 12-15 padding, clamped).
// 8 warps: half = w>>2 (0 gi / 1 gh), wm = (w>>1)&1 (m32), p = w&1 (n8).
// Combine: thread t -> (m = t>>2, j = t&3); writes h double-buffer + extras.
// ---------------------------------------------------------------------------
__device__ __forceinline__ void gates_fused(
    char* smem, int tid, int jb,
    const __half* __restrict__ A1h, const __half* __restrict__ A1l,
    const __half* __restrict__ A2h, const __half* __restrict__ A2l,
    const __half* __restrict__ Wih, const __half* __restrict__ Whh,
    const float* __restrict__ bih, const float* __restrict__ bhh,
    const float* __restrict__ hOldf,
    float* __restrict__ hNewf, __half* __restrict__ hNewh, __half* __restrict__ hNewl,
    bool isL1, int step,
    const int* __restrict__ tids, const float* __restrict__ embed)
{
    const uint32_t sb = smem_to_u32(smem);
    const int lane = tid & 31;
    const int w    = tid >> 5;
    const int half = w >> 2;       // 0 = gi (A1), 1 = gh (A2)
    const int wm   = (w >> 1) & 1; // m32 half
    const int p    = w & 1;        // n8 tile within 16
    const int gq   = lane >> 3;

    float d[2][4] = {};

    // loader indices
    const int arow = tid >> 2;     // 0..63
    const int ach  = tid & 3;      // 16B chunk
    // W loader (tid < 128): rW = tid>>2 in 0..31 (0-15 Wih tile, 16-31 Whh)
    const int rW   = tid >> 2;
    const int rloc = (rW < 16) ? rW : rW - 16;
    const int rclp = (rloc < 12) ? rloc : 11;          // clamp pad rows
    const long wgrow = (long)((rclp >> 2) * 512 + jb + (rclp & 3)) * DH;
    const __half* wsrc = (rW < 16) ? Wih : Whh;
    const uint32_t wdst = (rW < 16) ? GA_WI(0) : GA_WH(0);  // +st*1280 added later
    const uint32_t wrowoff = rloc * 80 + ach * 16;

    auto load_tile = [&](int t) {
        const int st = t % 3;
        const int k0 = t * 32;
        uint32_t d1 = sb + GA_A1H(st) + arow * 80 + ach * 16;
        asm volatile("cp.async.ca.shared.global [%0], [%1], 16;"
                     :: "r"(d1), "l"(&A1h[arow * DH + k0 + ach * 8]));
        uint32_t d2 = sb + GA_A1L(st) + arow * 80 + ach * 16;
        asm volatile("cp.async.ca.shared.global [%0], [%1], 16;"
                     :: "r"(d2), "l"(&A1l[arow * DH + k0 + ach * 8]));
        uint32_t d3 = sb + GA_A2H(st) + arow * 80 + ach * 16;
        asm volatile("cp.async.ca.shared.global [%0], [%1], 16;"
                     :: "r"(d3), "l"(&A2h[arow * DH + k0 + ach * 8]));
        uint32_t d4 = sb + GA_A2L(st) + arow * 80 + ach * 16;
        asm volatile("cp.async.ca.shared.global [%0], [%1], 16;"
                     :: "r"(d4), "l"(&A2l[arow * DH + k0 + ach * 8]));
        if (tid < 128) {
            uint32_t dw = sb + wdst + st * 1280 + wrowoff;
            asm volatile("cp.async.ca.shared.global [%0], [%1], 16;"
                         :: "r"(dw), "l"(&wsrc[wgrow + k0 + ach * 8]));
        }
    };

    auto compute = [&](int t) {
        const int st = t % 3;
        const uint32_t aHoff = half ? GA_A2H(st) : GA_A1H(st);
        const uint32_t aLoff = half ? GA_A2L(st) : GA_A1L(st);
        const uint32_t woff  = half ? GA_WH(st)  : GA_WI(st);
        #pragma unroll
        for (int ks = 0; ks < 2; ks++) {
            uint32_t ahi[2][4], alo[2][4], bt[4];
            #pragma unroll
            for (int mi = 0; mi < 2; mi++) {
                int row = wm * 32 + mi * 16 + (lane & 15);
                int kc  = ks * 32 + (lane >> 4) * 16;
                ldsm4(ahi[mi], sb + aHoff + row * 80 + kc);
                ldsm4(alo[mi], sb + aLoff + row * 80 + kc);
            }
            {
                int rowB = (gq >> 1) * 8 + (lane & 7);
                int kcB  = ks * 32 + (gq & 1) * 16;
                ldsm4(bt, sb + woff + rowB * 80 + kcB);
            }
            uint32_t bf[2] = { bt[2 * p], bt[2 * p + 1] };
            #pragma unroll
            for (int mi = 0; mi < 2; mi++) {
                mma16816h(d[mi], ahi[mi], bf);
                mma16816h(d[mi], alo[mi], bf);
            }
        }
    };

    // prologue: 3 stages in flight
    load_tile(0); asm volatile("cp.async.commit_group;" ::: "memory");
    load_tile(1); asm volatile("cp.async.commit_group;" ::: "memory");
    load_tile(2); asm volatile("cp.async.commit_group;" ::: "memory");

    #pragma unroll 1
    for (int t = 0; t < 16; t++) {
        asm volatile("cp.async.wait_group 2;" ::: "memory");
        __syncthreads();
        compute(t);
        __syncthreads();
        if (t + 3 < 16) load_tile(t + 3);
        asm volatile("cp.async.commit_group;" ::: "memory");
    }

    // stage gates to epi (aliases stage-0 region; compute fully done)
    float (*epi)[25] = reinterpret_cast<float(*)[25]>(smem);
    {
        const int colw = p * 8 + (lane & 3) * 2;
        if (colw < 12) {
            const int cb = half * 12 + colw;
            #pragma unroll
            for (int mi = 0; mi < 2; mi++) {
                int r = wm * 32 + mi * 16 + (lane >> 2);
                epi[r][cb]     = d[mi][0];
                epi[r][cb + 1] = d[mi][1];
                epi[r + 8][cb]     = d[mi][2];
                epi[r + 8][cb + 1] = d[mi][3];
            }
        }
    }
    __syncthreads();

    // fused combine: one (m, j) per thread
    {
        int m = tid >> 2, j = tid & 3, jj = jb + j;
        const float* E = epi[m];
        float r = sigmoidf_(E[j]     + bih[jj]        + E[12 + j] + bhh[jj]);
        float z = sigmoidf_(E[4 + j] + bih[512 + jj]  + E[16 + j] + bhh[512 + jj]);
        float n = tanhf(E[8 + j] + bih[1024 + jj] + r * (E[20 + j] + bhh[1024 + jj]));
        float hn = (1.f - z) * n + z * hOldf[m * DH + jj];
        int idx = m * DH + jj;
        hNewf[idx] = hn;
        __half hi = __float2half(hn);
        hNewh[idx] = hi;
        hNewl[idx] = __float2half(hn - __half2float(hi));
        if (isL1) {
            g_Ah[(m * NDRAFT + step) * DH + jj] = hi;
            if (step < NDRAFT - 1) {
                float xv = embed[(long)tids[m * NDRAFT + step] * DH + jj];
                __half xh = __float2half(xv);
                g_xh[idx] = xh;
                g_xl[idx] = __float2half(xv - __half2float(xh));
            }
        }
    }
}

// ---------------------------------------------------------------------------
__global__ __launch_bounds__(256) void gru_fused(
    const float* __restrict__ hidden, const int* __restrict__ tids,
    const float* __restrict__ ip_w,  const float* __restrict__ ip_b,
    const float* __restrict__ w_ih0, const float* __restrict__ w_hh0,
    const float* __restrict__ b_ih0, const float* __restrict__ b_hh0,
    const float* __restrict__ w_ih1, const float* __restrict__ w_hh1,
    const float* __restrict__ b_ih1, const float* __restrict__ b_hh1,
    const float* __restrict__ embed)
{
    extern __shared__ char smem[];
    const int tid = threadIdx.x;
    const int c = blockIdx.x;

    // ---- phase -1: convert GRU weights to fp16 (once per call) ----
    for (int i = c * 256 + tid; i < G3 * DH; i += GRIDN * 256) {
        g_wih0h[i] = __float2half(w_ih0[i]);
        g_whh0h[i] = __float2half(w_hh0[i]);
        g_wih1h[i] = __float2half(w_ih1[i]);
        g_whh1h[i] = __float2half(w_hh1[i]);
    }

    // ---- phase 0: input projection partials (64x64 n-tile, 256-k slice) ----
    {
        float (*As)[64] = reinterpret_cast<float(*)[64]>(smem);
        float (*Ws)[64] = reinterpret_cast<float(*)[64]>(smem + 8192);
        const int n0 = (c & 7) * 64;
        const int kbase = (c >> 3) * 256;
        const int ty = tid >> 4, tx = tid & 15;
        float acc[4][4] = {};
        for (int kt = 0; kt < 256; kt += 32) {
            #pragma unroll
            for (int i = 0; i < 2; i++) {
                int f = tid + i * 256;
                int m = f >> 3;
                int kq = (f & 7) << 2;
                float4 va = *reinterpret_cast<const float4*>(&hidden[m * HID + kbase + kt + kq]);
                As[kq + 0][m] = va.x; As[kq + 1][m] = va.y;
                As[kq + 2][m] = va.z; As[kq + 3][m] = va.w;
                float4 vw = *reinterpret_cast<const float4*>(&ip_w[(n0 + m) * HID + kbase + kt + kq]);
                Ws[kq + 0][m] = vw.x; Ws[kq + 1][m] = vw.y;
                Ws[kq + 2][m] = vw.z; Ws[kq + 3][m] = vw.w;
            }
            __syncthreads();
            #pragma unroll
            for (int kk = 0; kk < 32; kk++) {
                float a[4], b[4];
                #pragma unroll
                for (int i = 0; i < 4; i++) { a[i] = As[kk][ty * 4 + i]; b[i] = Ws[kk][tx * 4 + i]; }
                #pragma unroll
                for (int i = 0; i < 4; i++)
                    #pragma unroll
                    for (int j = 0; j < 4; j++) acc[i][j] += a[i] * b[j];
            }
            __syncthreads();
        }
        float* part = g_part + (c >> 3) * (B_ * DH);
        #pragma unroll
        for (int i = 0; i < 4; i++)
            #pragma unroll
            for (int j = 0; j < 4; j++)
                part[(ty * 4 + i) * DH + n0 + tx * 4 + j] = acc[i][j];
    }
    grid_barrier(tid);

    // ---- phase 1: reduce 16 partials + bias; init slot 0 + x = 0 ----
    {
        int idx = c * 256 + tid;
        float s = 0.f;
        #pragma unroll
        for (int p = 0; p < 16; p++) s += g_part[p * (B_ * DH) + idx];
        s += ip_b[idx & (DH - 1)];
        g_h0f[0][idx] = s;
        g_h1f[0][idx] = s;
        __half hi = __float2half(s);
        __half lo = __float2half(s - __half2float(hi));
        g_h0h[0][idx] = hi; g_h0l[0][idx] = lo;
        g_h1h[0][idx] = hi; g_h1l[0][idx] = lo;
        g_xh[idx] = __float2half(0.f);
        g_xl[idx] = __float2half(0.f);
    }
    grid_barrier(tid);

    // ---- 4 draft steps x 2 GRU layers, combine fused ----
    const int jb = c * 4;
    for (int step = 0; step < NDRAFT; step++) {
        const int p = step & 1;
        // layer 0: gi = x @ Wih0^T, gh = h0[p] @ Whh0^T -> h0[1-p]
        gates_fused(smem, tid, jb,
                    g_xh, g_xl, g_h0h[p], g_h0l[p],
                    g_wih0h, g_whh0h, b_ih0, b_hh0,
                    g_h0f[p], g_h0f[1 - p], g_h0h[1 - p], g_h0l[1 - p],
                    false, step, tids, embed);
        grid_barrier(tid);
        // layer 1: gi = h0[1-p] @ Wih1^T, gh = h1[p] @ Whh1^T -> h1[1-p]
        gates_fused(smem, tid, jb,
                    g_h0h[1 - p], g_h0l[1 - p], g_h1h[p], g_h1l[p],
                    g_wih1h, g_whh1h, b_ih1, b_hh1,
                    g_h1f[p], g_h1f[1 - p], g_h1h[1 - p], g_h1l[1 - p],
                    true, step, tids, embed);
        grid_barrier(tid);
    }
}

// ---------------------------------------------------------------------------
// Logits GEMM via single fp16 mma.sync (fp32 accum) — round-10..12 proven.
// CTA tile 128(M) x 128(N) x 32(K); 8 warps (2 M x 4 N); warp tile 64x32.
// smem 40KB -> 2 CTAs/SM. grid (2, 393).
// ---------------------------------------------------------------------------
#define ROWB 80
#define AH_OFF(s) ((s) * 10240)
#define BH_OFF(s) (20480 + (s) * 10240)
#define LOGITS_SMEM 40960

__global__ __launch_bounds__(256, 2) void logits_mma(const float* __restrict__ W,
                                                     float* __restrict__ out)
{
    extern __shared__ char smem[];
    const uint32_t sbase = smem_to_u32(smem);
    const int tid  = threadIdx.x;
    const int lane = tid & 31;
    const int w    = tid >> 5;
    const int wm   = w >> 2;
    const int wn   = w & 3;
    const int m0   = blockIdx.x * 128;
    const int n0   = blockIdx.y * 128;

    float d[4][4][4];
    #pragma unroll
    for (int i = 0; i < 4; i++)
        #pragma unroll
        for (int j = 0; j < 4; j++)
            #pragma unroll
            for (int q = 0; q < 4; q++) d[i][j][q] = 0.f;

    float4 breg[4];

    auto cpasync_A = [&](int c, int s) {
        const int k0 = c * 32;
        #pragma unroll
        for (int i = 0; i < 2; i++) {
            int idx = tid + i * 256;
            int row = idx >> 2;
            int ch  = idx & 3;
            const __half* sh = &g_Ah[(m0 + row) * DH + k0 + ch * 8];
            uint32_t dh = sbase + AH_OFF(s) + row * ROWB + ch * 16;
            asm volatile("cp.async.ca.shared.global [%0], [%1], 16;" :: "r"(dh), "l"(sh));
        }
        asm volatile("cp.async.commit_group;" ::: "memory");
    };

    auto ldg_B = [&](int c) {
        const int k0 = c * 32;
        #pragma unroll
        for (int i = 0; i < 4; i++) {
            int idx = tid + i * 256;
            int row = idx >> 3;
            int col = (idx & 7) * 4;
            int vr = n0 + row;
            breg[i] = (vr < VOCAB)
                ? *reinterpret_cast<const float4*>(&W[(long)vr * DH + k0 + col])
                : make_float4(0.f, 0.f, 0.f, 0.f);
        }
    };

    auto sts_B = [&](int s) {
        #pragma unroll
        for (int i = 0; i < 4; i++) {
            int idx = tid + i * 256;
            int row = idx >> 3;
            int col = (idx & 7) * 4;
            float4 v = breg[i];
            uint2 ph;
            ph.x = pack_f16x2(__float2half(v.x), __float2half(v.y));
            ph.y = pack_f16x2(__float2half(v.z), __float2half(v.w));
            *reinterpret_cast<uint2*>(smem + BH_OFF(s) + row * ROWB + col * 2) = ph;
        }
    };

    auto compute = [&](int s) {
        #pragma unroll
        for (int ks = 0; ks < 2; ks++) {
            uint32_t ah[4][4];
            #pragma unroll
            for (int mi = 0; mi < 4; mi++) {
                int row = wm * 64 + mi * 16 + (lane & 15);
                int kc  = ks * 32 + (lane >> 4) * 16;
                ldsm4(ah[mi], sbase + AH_OFF(s) + row * ROWB + kc);
            }
            uint32_t bh[4][2];
            #pragma unroll
            for (int nb = 0; nb < 2; nb++) {
                int gq  = lane >> 3;
                int row = wn * 32 + nb * 16 + (gq >> 1) * 8 + (lane & 7);
                int kc  = ks * 32 + (gq & 1) * 16;
                ldsm4(&bh[nb * 2][0], sbase + BH_OFF(s) + row * ROWB + kc);
            }
            #pragma unroll
            for (int mi = 0; mi < 4; mi++)
                #pragma unroll
                for (int ni = 0; ni < 4; ni++)
                    mma16816h(d[mi][ni], ah[mi], bh[ni]);
        }
    };

    cpasync_A(0, 0);
    ldg_B(0);
    sts_B(0);
    asm volatile("cp.async.wait_group 0;" ::: "memory");
    __syncthreads();

    #pragma unroll 1
    for (int c = 0; c < 16; c++) {
        int s = c & 1;
        if (c + 1 < 16) {
            cpasync_A(c + 1, 1 - s);
            ldg_B(c + 1);
        }
        compute(s);
        if (c + 1 < 16) {
            sts_B(1 - s);
            asm volatile("cp.async.wait_group 0;" ::: "memory");
        }
        __syncthreads();
    }

    const int g  = lane >> 2;
    const int i2 = (lane & 3) * 2;
    #pragma unroll
    for (int mi = 0; mi < 4; mi++) {
        int r0 = m0 + wm * 64 + mi * 16 + g;
        long rb0 = (long)r0 * VOCAB;
        long rb1 = (long)(r0 + 8) * VOCAB;
        #pragma unroll
        for (int ni = 0; ni < 4; ni++) {
            int col = n0 + wn * 32 + ni * 8 + i2;
            if (col < VOCAB) {
                out[rb0 + col] = d[mi][ni][0];
                out[rb1 + col] = d[mi][ni][2];
                if (col + 1 < VOCAB) {
                    out[rb0 + col + 1] = d[mi][ni][1];
                    out[rb1 + col + 1] = d[mi][ni][3];
                }
            }
        }
    }
}

// ---------------------------------------------------------------------------
extern "C" void kernel_launch(void* const* d_in, const int* in_sizes, int n_in,
                              void* d_out, int out_size)
{
    const float* hidden = (const float*)d_in[0];
    const int*   tids   = (const int*)  d_in[1];
    const float* ip_w   = (const float*)d_in[2];
    const float* ip_b   = (const float*)d_in[3];
    const float* w_ih0  = (const float*)d_in[4];
    const float* w_hh0  = (const float*)d_in[5];
    const float* b_ih0  = (const float*)d_in[6];
    const float* b_hh0  = (const float*)d_in[7];
    const float* w_ih1  = (const float*)d_in[8];
    const float* w_hh1  = (const float*)d_in[9];
    const float* b_ih1  = (const float*)d_in[10];
    const float* b_hh1  = (const float*)d_in[11];
    const float* embed  = (const float*)d_in[12];
    const float* out_w  = (const float*)d_in[13];
    float* out = (float*)d_out;

    cudaFuncSetAttribute(gru_fused, cudaFuncAttributeMaxDynamicSharedMemorySize, GRU_SMEM);
    cudaFuncSetAttribute(logits_mma, cudaFuncAttributeMaxDynamicSharedMemorySize, LOGITS_SMEM);

    gru_fused<<<GRIDN, 256, GRU_SMEM>>>(hidden, tids, ip_w, ip_b,
                                        w_ih0, w_hh0, b_ih0, b_hh0,
                                        w_ih1, w_hh1, b_ih1, b_hh1, embed);

    logits_mma<<<dim3(2, (VOCAB + 127) / 128), 256, LOGITS_SMEM>>>(out_w, out);
}